// round 1
// baseline (speedup 1.0000x reference)
#include <cuda_runtime.h>
#include <cuda_bf16.h>

// Problem shapes (fixed)
#define Bq 8
#define Eq 8
#define Cq 1024
#define Iq 128
#define Oq 256
#define Tq 8192

// GEMM tile config
#define BM 128
#define BN 64
#define BK 128           // == Iq, full K resident
#define NTHREADS 256

// ---------------------------------------------------------------------------
// Zero-init output (poisoned to 0xAA by harness)
// ---------------------------------------------------------------------------
__global__ void zero_kernel(float* __restrict__ out, int n4) {
    float4 z = make_float4(0.f, 0.f, 0.f, 0.f);
    for (int i = blockIdx.x * blockDim.x + threadIdx.x; i < n4;
         i += gridDim.x * blockDim.x) {
        reinterpret_cast<float4*>(out)[i] = z;
    }
}

// ---------------------------------------------------------------------------
// Per-expert GEMM + bias + gate + atomic scatter-add
//   y[b,e,c,o] = (sum_i x[b,e,c,i] * w[e,o,i] + bias[o]) * gate[b,e,c]
//   out[b, idx[b,e,c], o] += y[b,e,c,o]
// Grid: (Oq/BN, Cq/BM, Bq*Eq), 256 threads, 8x4 microtile per thread.
// ---------------------------------------------------------------------------
extern "C" __global__ void __launch_bounds__(NTHREADS, 2)
moe_gemm_scatter(const float* __restrict__ x,
                 const int*   __restrict__ idx,
                 const float* __restrict__ gate,
                 const float* __restrict__ w,
                 const float* __restrict__ bias,
                 float* __restrict__ out) {
    extern __shared__ float smem[];
    float* As = smem;              // [BK][BM] k-major
    float* Bs = smem + BK * BM;    // [BK][BN] k-major

    const int be = blockIdx.z;           // b*Eq + e
    const int b  = be >> 3;
    const int e  = be & 7;
    const int m0 = blockIdx.y * BM;      // capacity-row offset
    const int n0 = blockIdx.x * BN;      // output-feature offset
    const int tid = threadIdx.x;

    const float* xb = x + ((long)be * Cq + m0) * Iq;        // BM rows of 128
    const float* wb = w + ((long)e * Oq + n0) * Iq;         // BN rows of 128

    // Load A tile: BM x 128 -> As[k][m] (transposed into k-major)
    // BM*32 float4 loads, 16 per thread
    #pragma unroll
    for (int t = tid; t < BM * 32; t += NTHREADS) {
        int r  = t >> 5;
        int c4 = t & 31;
        float4 v = reinterpret_cast<const float4*>(xb + r * Iq)[c4];
        int k = c4 * 4;
        As[(k + 0) * BM + r] = v.x;
        As[(k + 1) * BM + r] = v.y;
        As[(k + 2) * BM + r] = v.z;
        As[(k + 3) * BM + r] = v.w;
    }
    // Load B tile: BN x 128 -> Bs[k][n]
    #pragma unroll
    for (int t = tid; t < BN * 32; t += NTHREADS) {
        int r  = t >> 5;
        int c4 = t & 31;
        float4 v = reinterpret_cast<const float4*>(wb + r * Iq)[c4];
        int k = c4 * 4;
        Bs[(k + 0) * BN + r] = v.x;
        Bs[(k + 1) * BN + r] = v.y;
        Bs[(k + 2) * BN + r] = v.z;
        Bs[(k + 3) * BN + r] = v.w;
    }
    __syncthreads();

    // Thread -> microtile mapping: 16 (m) x 16 (n) threads
    const int mt = tid >> 4;     // 0..15
    const int nt = tid & 15;     // 0..15
    const int tm = mt * 8;
    const int tn = nt * 4;

    float acc[8][4];
    #pragma unroll
    for (int i = 0; i < 8; i++)
        #pragma unroll
        for (int j = 0; j < 4; j++) acc[i][j] = 0.f;

    #pragma unroll 8
    for (int k = 0; k < BK; k++) {
        float4 a0 = *reinterpret_cast<const float4*>(&As[k * BM + tm]);
        float4 a1 = *reinterpret_cast<const float4*>(&As[k * BM + tm + 4]);
        float4 bv = *reinterpret_cast<const float4*>(&Bs[k * BN + tn]);
        float a[8] = {a0.x, a0.y, a0.z, a0.w, a1.x, a1.y, a1.z, a1.w};
        float bb[4] = {bv.x, bv.y, bv.z, bv.w};
        #pragma unroll
        for (int i = 0; i < 8; i++)
            #pragma unroll
            for (int j = 0; j < 4; j++)
                acc[i][j] = fmaf(a[i], bb[j], acc[i][j]);
    }

    // Epilogue: + bias, * gate, atomic scatter into out[b, token, o]
    float bs[4];
    #pragma unroll
    for (int j = 0; j < 4; j++) bs[j] = bias[n0 + tn + j];

    const float* gb = gate + (long)be * Cq + m0;
    const int*   ib = idx  + (long)be * Cq + m0;

    #pragma unroll
    for (int i = 0; i < 8; i++) {
        int   c = tm + i;
        float g = gb[c];
        int   tok = ib[c];
        float* op = out + ((long)b * Tq + tok) * Oq + n0 + tn;
        #pragma unroll
        for (int j = 0; j < 4; j++) {
            atomicAdd(op + j, (acc[i][j] + bs[j]) * g);
        }
    }
}

// ---------------------------------------------------------------------------
// kernel_launch: zero output, then fused GEMM+scatter
// Inputs (metadata order): x_expert f32, expert_indices i32, expert_gate f32,
//                          weight f32, bias f32, num_tokens i32
// ---------------------------------------------------------------------------
extern "C" void kernel_launch(void* const* d_in, const int* in_sizes, int n_in,
                              void* d_out, int out_size) {
    const float* x    = (const float*)d_in[0];
    const int*   idx  = (const int*)  d_in[1];
    const float* gate = (const float*)d_in[2];
    const float* w    = (const float*)d_in[3];
    const float* bias = (const float*)d_in[4];
    float* out = (float*)d_out;

    // Zero the (B, T, O) output
    int n4 = (Bq * Tq * Oq) / 4;   // 4,194,304 float4
    zero_kernel<<<4096, 256>>>(out, n4);

    // GEMM + scatter
    const int smem_bytes = (BK * BM + BK * BN) * sizeof(float);  // 98304
    cudaFuncSetAttribute(moe_gemm_scatter,
                         cudaFuncAttributeMaxDynamicSharedMemorySize, smem_bytes);
    dim3 grid(Oq / BN, Cq / BM, Bq * Eq);   // (4, 8, 64)
    moe_gemm_scatter<<<grid, NTHREADS, smem_bytes>>>(x, idx, gate, w, bias, out);
}

// round 3
// speedup vs baseline: 4.5398x; 4.5398x over previous
#include <cuda_runtime.h>
#include <cstdint>

// Problem shapes (fixed)
#define Bq 8
#define Eq 8
#define Cq 1024
#define Iq 128
#define Oq 256
#define Tq 8192

#define NTHREADS 256
#define BM 128
#define BN 128

// smem layout: bias[256] at 0, A tile at 1024 (64KB), B tile at 66560 (64KB)
#define SMEM_BIAS 0
#define SMEM_A    1024
#define SMEM_B    (1024 + 128 * 512)
#define SMEM_TOTAL (SMEM_B + 128 * 512)   // 132096

__device__ __forceinline__ uint32_t smem_u32(const void* p) {
    uint32_t a;
    asm("{ .reg .u64 t; cvta.to.shared.u64 t, %1; cvt.u32.u64 %0, t; }"
        : "=r"(a) : "l"(p));
    return a;
}

__device__ __forceinline__ uint32_t f2tf32(float f) {
    uint32_t r;
    asm("cvt.rna.tf32.f32 %0, %1;" : "=r"(r) : "f"(f));
    return r;
}

#define LDSM_X4(r0, r1, r2, r3, addr) \
    asm volatile("ldmatrix.sync.aligned.m8n8.x4.shared.b16 {%0,%1,%2,%3}, [%4];" \
                 : "=r"(r0), "=r"(r1), "=r"(r2), "=r"(r3) : "r"(addr))

#define MMA_TF32(c, a, b0, b1) \
    asm volatile("mma.sync.aligned.m16n8k8.row.col.f32.tf32.tf32.f32 " \
                 "{%0,%1,%2,%3}, {%4,%5,%6,%7}, {%8,%9}, {%0,%1,%2,%3};" \
                 : "+f"((c)[0]), "+f"((c)[1]), "+f"((c)[2]), "+f"((c)[3]) \
                 : "r"((a)[0]), "r"((a)[1]), "r"((a)[2]), "r"((a)[3]), \
                   "r"(b0), "r"(b1))

// ---------------------------------------------------------------------------
// Zero-init output (harness poisons d_out to 0xAA)
// ---------------------------------------------------------------------------
__global__ void zero_kernel(float* __restrict__ out, int n4) {
    float4 z = make_float4(0.f, 0.f, 0.f, 0.f);
    for (int i = blockIdx.x * blockDim.x + threadIdx.x; i < n4;
         i += gridDim.x * blockDim.x) {
        reinterpret_cast<float4*>(out)[i] = z;
    }
}

// ---------------------------------------------------------------------------
// tf32 mma.sync GEMM + bias + gate + red.v2 scatter
// Grid: (Oq/BN=2, Cq/BM=8, 64).  Block: 256 threads (8 warps, 4m x 2n).
// Warp tile 32(m) x 64(n); per warp: 2 m16-tiles x 8 n8-tiles x 16 k8-steps.
// ---------------------------------------------------------------------------
extern "C" __global__ void __launch_bounds__(NTHREADS, 1)
moe_mma_scatter(const float* __restrict__ x,
                const int*   __restrict__ idx,
                const float* __restrict__ gate,
                const float* __restrict__ w,
                const float* __restrict__ bias,
                float* __restrict__ out) {
    extern __shared__ char smem[];
    const uint32_t sbase = smem_u32(smem);
    const int tid  = threadIdx.x;
    const int wid  = tid >> 5;
    const int lane = tid & 31;

    const int be = blockIdx.z;            // b*Eq + e
    const int b  = be >> 3;
    const int e  = be & 7;
    const int m0 = blockIdx.y * BM;       // capacity-row offset
    const int n_base = blockIdx.x * BN;   // output-feature offset

    const float* xb = x + ((long)be * Cq + m0) * Iq;
    const float* wb = w + ((long)e * Oq + n_base) * Iq;

    // --- Load tiles: f32 -> tf32 (rna), row-major, 512B rows, chunk-XOR swizzle
    // element (r, c): offset = r*512 + (((c>>2) ^ (r&7))<<4) + (c&3)*4
    float* As = reinterpret_cast<float*>(smem + SMEM_A);
    float* Bs = reinterpret_cast<float*>(smem + SMEM_B);
    #pragma unroll
    for (int t = tid; t < 128 * 32; t += NTHREADS) {
        int r = t >> 5, c4 = t & 31;
        float4 v = reinterpret_cast<const float4*>(xb + r * Iq)[c4];
        uint4 p = make_uint4(f2tf32(v.x), f2tf32(v.y), f2tf32(v.z), f2tf32(v.w));
        int off = r * 128 + ((c4 ^ (r & 7)) << 2);     // in floats
        *reinterpret_cast<uint4*>(As + off) = p;
    }
    #pragma unroll
    for (int t = tid; t < 128 * 32; t += NTHREADS) {
        int r = t >> 5, c4 = t & 31;
        float4 v = reinterpret_cast<const float4*>(wb + r * Iq)[c4];
        uint4 p = make_uint4(f2tf32(v.x), f2tf32(v.y), f2tf32(v.z), f2tf32(v.w));
        int off = r * 128 + ((c4 ^ (r & 7)) << 2);
        *reinterpret_cast<uint4*>(Bs + off) = p;
    }
    if (tid < 256) reinterpret_cast<float*>(smem + SMEM_BIAS)[tid] = bias[tid];
    __syncthreads();

    // --- Warp/lane geometry ---
    const int m_w = (wid >> 1) * 32;      // warp row offset in tile
    const int n_w = (wid & 1) * 64;       // warp col offset in tile
    const int sub = lane >> 3;            // ldmatrix quad-tile id
    const int l7  = lane & 7;

    // ldmatrix lane base addresses (byte offsets, k-dependent chunk added later)
    // A x4 tiles: [m..m+7,kL] [m+8..15,kL] [m..m+7,kH] [m+8..15,kH]
    const int a_r[2] = { m_w + (sub & 1) * 8 + l7, m_w + 16 + (sub & 1) * 8 + l7 };
    const int a_kh = sub >> 1;            // +4 k for high tiles
    // B x4 tiles: [n..n+7,kL] [n..n+7,kH] [n+8..15,kL] [n+8..15,kH]
    const int b_kh = sub & 1;
    int b_n[4];
    #pragma unroll
    for (int jp = 0; jp < 4; jp++) b_n[jp] = n_w + jp * 16 + (sub >> 1) * 8 + l7;

    float acc[2][8][4];
    #pragma unroll
    for (int i = 0; i < 2; i++)
        #pragma unroll
        for (int j = 0; j < 8; j++)
            #pragma unroll
            for (int q = 0; q < 4; q++) acc[i][j][q] = 0.f;

    const uint32_t a_base = sbase + SMEM_A;
    const uint32_t b_base = sbase + SMEM_B;

    #pragma unroll
    for (int ks = 0; ks < 16; ks++) {
        const int kc = ks * 2;            // k0>>2 (chunk units)
        uint32_t Af[2][4];
        #pragma unroll
        for (int i = 0; i < 2; i++) {
            uint32_t chunk = (uint32_t)((kc + a_kh) ^ l7);
            uint32_t addr = a_base + a_r[i] * 512 + (chunk << 4);
            LDSM_X4(Af[i][0], Af[i][1], Af[i][2], Af[i][3], addr);
        }
        uint32_t Bf[4][4];
        #pragma unroll
        for (int jp = 0; jp < 4; jp++) {
            uint32_t chunk = (uint32_t)((kc + b_kh) ^ l7);
            uint32_t addr = b_base + b_n[jp] * 512 + (chunk << 4);
            LDSM_X4(Bf[jp][0], Bf[jp][1], Bf[jp][2], Bf[jp][3], addr);
        }
        #pragma unroll
        for (int i = 0; i < 2; i++)
            #pragma unroll
            for (int j = 0; j < 8; j++)
                MMA_TF32(acc[i][j], Af[i], Bf[j >> 1][(j & 1) * 2],
                         Bf[j >> 1][(j & 1) * 2 + 1]);
    }

    // --- Epilogue: bias + gate + red.v2 scatter ---
    const float* bias_s = reinterpret_cast<const float*>(smem + SMEM_BIAS);
    const float* gb = gate + (long)be * Cq + m0;
    const int*   ib = idx  + (long)be * Cq + m0;
    const int qrow  = lane >> 2;          // 0..7
    const int cpair = (lane & 3) * 2;

    #pragma unroll
    for (int i = 0; i < 2; i++) {
        #pragma unroll
        for (int half = 0; half < 2; half++) {
            int r = m_w + i * 16 + half * 8 + qrow;
            float g = gb[r];
            int tok = ib[r];
            float* op = out + ((long)b * Tq + tok) * Oq + n_base + n_w + cpair;
            #pragma unroll
            for (int j = 0; j < 8; j++) {
                int col = n_base + n_w + j * 8 + cpair;
                float v0 = (acc[i][j][half * 2 + 0] + bias_s[col])     * g;
                float v1 = (acc[i][j][half * 2 + 1] + bias_s[col + 1]) * g;
                asm volatile("red.global.add.v2.f32 [%0], {%1, %2};"
                             :: "l"(op + j * 8), "f"(v0), "f"(v1) : "memory");
            }
        }
    }
}

// ---------------------------------------------------------------------------
// kernel_launch
// Inputs: x_expert f32, expert_indices i32, expert_gate f32, weight f32,
//         bias f32, num_tokens i32 (unused)
// ---------------------------------------------------------------------------
extern "C" void kernel_launch(void* const* d_in, const int* in_sizes, int n_in,
                              void* d_out, int out_size) {
    const float* x    = (const float*)d_in[0];
    const int*   idx  = (const int*)  d_in[1];
    const float* gate = (const float*)d_in[2];
    const float* w    = (const float*)d_in[3];
    const float* bias = (const float*)d_in[4];
    float* out = (float*)d_out;

    int n4 = (Bq * Tq * Oq) / 4;
    zero_kernel<<<4096, 256>>>(out, n4);

    cudaFuncSetAttribute(moe_mma_scatter,
                         cudaFuncAttributeMaxDynamicSharedMemorySize, SMEM_TOTAL);
    dim3 grid(Oq / BN, Cq / BM, Bq * Eq);   // (2, 8, 64) = 1024 CTAs
    moe_mma_scatter<<<grid, NTHREADS, SMEM_TOTAL>>>(x, idx, gate, w, bias, out);
}